// round 2
// baseline (speedup 1.0000x reference)
#include <cuda_runtime.h>

// CorrelationMSELoss — B=8192 rows, L=1024 labels.
// out = mean((pred-label)^2) + sum_rows(row_loss)
// row_loss: mixed rows: (sum_pos e^{-p})(sum_neg e^{p}) / (n1*n0)
//           all-zero  : e^{-1} * (sum_neg e^{p}) / n0
//           all-one   : (sum_pos e^{-p}) / n1

static constexpr int B_ROWS = 8192;
static constexpr int L_COLS = 1024;
static constexpr int WARPS_PER_BLOCK = 8;
static constexpr int THREADS = WARPS_PER_BLOCK * 32;

// scratch accumulators (device globals: no allocation in kernel_launch)
__device__ double g_acc[2];  // [0] = sum of squared errors, [1] = sum of row losses

__global__ void k_init() {
    g_acc[0] = 0.0;
    g_acc[1] = 0.0;
}

__device__ __forceinline__ float ex2_approx(float x) {
    float r;
    asm("ex2.approx.ftz.f32 %0, %1;" : "=f"(r) : "f"(x));
    return r;
}

__global__ __launch_bounds__(THREADS) void k_main(const float* __restrict__ pred,
                                                  const float* __restrict__ label) {
    const int lane = threadIdx.x & 31;
    const int warp = threadIdx.x >> 5;
    const long row = (long)blockIdx.x * WARPS_PER_BLOCK + warp;

    const float4* p4 = reinterpret_cast<const float4*>(pred) + row * (L_COLS / 4);
    const float4* l4 = reinterpret_cast<const float4*>(label) + row * (L_COLS / 4);

    constexpr float L2E = 1.4426950408889634f;  // log2(e)

    float mse = 0.f, spos = 0.f, sneg = 0.f, none = 0.f;

#pragma unroll
    for (int i = 0; i < L_COLS / 4 / 32; ++i) {
        float4 p = p4[i * 32 + lane];
        float4 l = l4[i * 32 + lane];
        float pe[4] = {p.x, p.y, p.z, p.w};
        float le[4] = {l.x, l.y, l.z, l.w};
#pragma unroll
        for (int j = 0; j < 4; ++j) {
            float pv = pe[j], lv = le[j];
            float d = pv - lv;
            mse = fmaf(d, d, mse);
            // c = +log2e for label==0 (exp(+p)), -log2e for label==1 (exp(-p))
            float c = fmaf(lv, -2.f * L2E, L2E);
            float e = ex2_approx(pv * c);
            bool pos = lv > 0.5f;
            spos += pos ? e : 0.f;
            sneg += pos ? 0.f : e;
            none += lv;  // exact integer counting in fp32 (<= 1024)
        }
    }

    // full warp reduction (each warp owns one row)
#pragma unroll
    for (int off = 16; off; off >>= 1) {
        mse  += __shfl_xor_sync(0xffffffffu, mse, off);
        spos += __shfl_xor_sync(0xffffffffu, spos, off);
        sneg += __shfl_xor_sync(0xffffffffu, sneg, off);
        none += __shfl_xor_sync(0xffffffffu, none, off);
    }

    if (lane == 0) {
        float n1 = none;
        float n0 = (float)L_COLS - none;
        float loss;
        if (n1 == 0.f) {
            // s_zero = e^{-1} * s_neg
            loss = sneg * 0.36787944117144233f / fmaxf(n0, 1.f);
        } else if (n0 == 0.f) {
            loss = spos / n1;
        } else {
            loss = (spos * sneg) / (n1 * n0);
        }
        atomicAdd(&g_acc[1], (double)loss);
        atomicAdd(&g_acc[0], (double)mse);
    }
}

__global__ void k_final(float* __restrict__ out) {
    out[0] = (float)(g_acc[0] * (1.0 / ((double)B_ROWS * (double)L_COLS)) + g_acc[1]);
}

extern "C" void kernel_launch(void* const* d_in, const int* in_sizes, int n_in,
                              void* d_out, int out_size) {
    const float* pred  = (const float*)d_in[0];
    const float* label = (const float*)d_in[1];
    float* out = (float*)d_out;

    k_init<<<1, 1>>>();
    k_main<<<B_ROWS / WARPS_PER_BLOCK, THREADS>>>(pred, label);
    k_final<<<1, 1>>>(out);
}

// round 3
// speedup vs baseline: 2.7494x; 2.7494x over previous
#include <cuda_runtime.h>

// CorrelationMSELoss — B=8192 rows, L=1024 labels, single fused kernel.
// out = mean((pred-label)^2) + sum_rows(row_loss)

static constexpr int B_ROWS = 8192;
static constexpr int L_COLS = 1024;
static constexpr int WARPS_PER_BLOCK = 8;
static constexpr int THREADS = WARPS_PER_BLOCK * 32;
static constexpr int GRID = B_ROWS / WARPS_PER_BLOCK;  // 1024 blocks, one wave

// Per-block partials (fully rewritten every launch -> no init kernel needed)
__device__ float g_part_mse[GRID];
__device__ float g_part_loss[GRID];
__device__ unsigned int g_count = 0;  // reset to 0 by last block each launch

__device__ __forceinline__ float ex2_approx(float x) {
    float r;
    asm("ex2.approx.ftz.f32 %0, %1;" : "=f"(r) : "f"(x));
    return r;
}

__global__ __launch_bounds__(THREADS) void k_fused(const float* __restrict__ pred,
                                                   const float* __restrict__ label,
                                                   float* __restrict__ out) {
    const int lane = threadIdx.x & 31;
    const int warp = threadIdx.x >> 5;
    const int row = blockIdx.x * WARPS_PER_BLOCK + warp;

    const float4* p4 = reinterpret_cast<const float4*>(pred) + (long)row * (L_COLS / 4);
    const float4* l4 = reinterpret_cast<const float4*>(label) + (long)row * (L_COLS / 4);

    constexpr float L2E = 1.4426950408889634f;  // log2(e)

    float mse = 0.f, spos = 0.f, stot = 0.f, none = 0.f;

#pragma unroll
    for (int i = 0; i < L_COLS / 4 / 32; ++i) {
        float4 p = p4[i * 32 + lane];
        float4 l = l4[i * 32 + lane];
        float pe[4] = {p.x, p.y, p.z, p.w};
        float le[4] = {l.x, l.y, l.z, l.w};
#pragma unroll
        for (int j = 0; j < 4; ++j) {
            float pv = pe[j], lv = le[j];
            float d = pv - lv;
            mse = fmaf(d, d, mse);
            float t = pv * L2E;                 // log2(e) * p
            float arg = fmaf(lv, -2.f * t, t);  // +t for lv=0, -t for lv=1
            float e = ex2_approx(arg);
            stot += e;                          // sum over all labels
            spos = fmaf(lv, e, spos);           // sum over positive labels
            none += lv;                         // exact integer count
        }
    }

    // warp reduction (warp owns one row)
#pragma unroll
    for (int off = 16; off; off >>= 1) {
        mse  += __shfl_xor_sync(0xffffffffu, mse, off);
        spos += __shfl_xor_sync(0xffffffffu, spos, off);
        stot += __shfl_xor_sync(0xffffffffu, stot, off);
        none += __shfl_xor_sync(0xffffffffu, none, off);
    }

    __shared__ float s_mse[WARPS_PER_BLOCK];
    __shared__ float s_loss[WARPS_PER_BLOCK];
    __shared__ bool s_last;

    if (lane == 0) {
        float n1 = none;
        float n0 = (float)L_COLS - none;
        float sneg = stot - spos;
        float loss;
        if (n1 == 0.f) {
            loss = sneg * 0.36787944117144233f / fmaxf(n0, 1.f);  // e^{-1} * s_neg / n0
        } else if (n0 == 0.f) {
            loss = spos / n1;
        } else {
            loss = (spos * sneg) / (n1 * n0);
        }
        s_mse[warp] = mse;
        s_loss[warp] = loss;
    }
    __syncthreads();

    // warp 0 folds the 8 per-warp results into the block partial
    if (warp == 0 && lane < WARPS_PER_BLOCK) {
        float bm = s_mse[lane];
        float bl = s_loss[lane];
#pragma unroll
        for (int off = 4; off; off >>= 1) {
            bm += __shfl_xor_sync(0x000000ffu, bm, off);
            bl += __shfl_xor_sync(0x000000ffu, bl, off);
        }
        if (lane == 0) {
            g_part_mse[blockIdx.x] = bm;
            g_part_loss[blockIdx.x] = bl;
        }
    }

    // last-block final reduction (threadfence-reduction pattern)
    if (threadIdx.x == 0) {
        __threadfence();
        unsigned int prev = atomicAdd(&g_count, 1u);
        s_last = (prev == (unsigned)gridDim.x - 1u);
    }
    __syncthreads();

    if (s_last) {
        double dm = 0.0, dl = 0.0;
#pragma unroll
        for (int i = 0; i < GRID / THREADS; ++i) {
            int idx = i * THREADS + threadIdx.x;
            dm += (double)g_part_mse[idx];
            dl += (double)g_part_loss[idx];
        }
#pragma unroll
        for (int off = 16; off; off >>= 1) {
            dm += __shfl_xor_sync(0xffffffffu, dm, off);
            dl += __shfl_xor_sync(0xffffffffu, dl, off);
        }
        __shared__ double sd_m[WARPS_PER_BLOCK];
        __shared__ double sd_l[WARPS_PER_BLOCK];
        if (lane == 0) {
            sd_m[warp] = dm;
            sd_l[warp] = dl;
        }
        __syncthreads();
        if (threadIdx.x == 0) {
            double tm = 0.0, tl = 0.0;
#pragma unroll
            for (int w = 0; w < WARPS_PER_BLOCK; ++w) {
                tm += sd_m[w];
                tl += sd_l[w];
            }
            out[0] = (float)(tm * (1.0 / ((double)B_ROWS * (double)L_COLS)) + tl);
            g_count = 0;  // reset for next graph replay
        }
    }
}

extern "C" void kernel_launch(void* const* d_in, const int* in_sizes, int n_in,
                              void* d_out, int out_size) {
    const float* pred  = (const float*)d_in[0];
    const float* label = (const float*)d_in[1];
    float* out = (float*)d_out;
    k_fused<<<GRID, THREADS>>>(pred, label, out);
}